// round 3
// baseline (speedup 1.0000x reference)
#include <cuda_runtime.h>
#include <cstdint>

// resRNN: x(256,1024,8), W1(521,512), b1(512), W2(512,1), b2(1)
// out = [output(256,1024,1) | implied_storage(256,1024,1)]
//
// 128 CTAs = 16 rowgroups x 8 colgroups. Cluster(8) = one rowgroup.
// Each CTA: 16 batch rows x 64 hidden cols, W1 slice resident in smem.
// 8 warps split K=544 (68 each), fma.rn.f32x2 packed accumulators.

#define TPB 256

static __device__ float g_hx[2][256][512];       // double-buffered hidden state
static __device__ float g_part[2][16][8][16];    // per-(rg,cg,row) readout partials

// shared memory layout (float offsets)
#define OFF_W    0              // 544*64   = 34816 floats
#define OFF_IT   34816          // 544*18   =  9792 floats (inpT, stride 18)
#define OFF_RED  44608          // 8*16*68  =  8704 floats
#define OFF_B1   53312          // 64
#define OFF_W2   53376          // 64
#define OFF_X0   53440          // 16
#define OFF_S    53456          // 16
#define OFF_OUT  53472          // 16
#define SMEM_FLOATS 53488
#define SMEM_BYTES (SMEM_FLOATS * 4)

__global__ void __cluster_dims__(8, 1, 1) __launch_bounds__(256, 1)
resRNN_kernel(const float* __restrict__ x, const float* __restrict__ W1,
              const float* __restrict__ b1, const float* __restrict__ W2,
              const float* __restrict__ b2, float* __restrict__ dout)
{
    extern __shared__ float sm[];
    float* Wsm    = sm + OFF_W;
    float* inpT   = sm + OFF_IT;
    float* red    = sm + OFF_RED;
    float* b1s    = sm + OFF_B1;
    float* w2s    = sm + OFF_W2;
    float* x0s    = sm + OFF_X0;
    float* s_sm   = sm + OFF_S;
    float* out_sm = sm + OFF_OUT;

    const int tid  = threadIdx.x;
    const int warp = tid >> 5;
    const int lane = tid & 31;
    const int cg   = blockIdx.x;   // colgroup 0..7
    const int rg   = blockIdx.y;   // rowgroup 0..15
    const int row0 = rg * 16;

    // ---- init: load W1 slice [544 x 64] (zero-pad k>=521), zero inpT ----
    for (int i = tid; i < 544 * 16; i += TPB) {
        int k = i >> 4, f4 = i & 15;
        float4 v = make_float4(0.f, 0.f, 0.f, 0.f);
        if (k < 521) v = *(const float4*)&W1[k * 512 + cg * 64 + f4 * 4];
        *(float4*)&Wsm[k * 64 + f4 * 4] = v;
    }
    for (int i = tid; i < 544 * 18; i += TPB) inpT[i] = 0.f;
    if (tid < 64) { b1s[tid] = b1[cg * 64 + tid]; w2s[tid] = W2[cg * 64 + tid]; }
    if (tid < 16) { s_sm[tid] = 0.f; out_sm[tid] = 0.f; }
    const float b2v = b2[0];
    float* outp = dout;
    float* stop = dout + 256 * 1024;
    __syncthreads();

    for (int t = 0; t < 1024; ++t) {
        const int pw = t & 1;        // write parity
        const int pr = pw ^ 1;       // read parity = (t-1)&1

        // ---- Phase A: gather out_{t-1}, transpose hx into inpT, load x_t ----
        if (t > 0) {
            if (tid < 16) {
                float o = b2v;
                #pragma unroll
                for (int g = 0; g < 8; ++g) o += __ldcg(&g_part[pr][rg][g][tid]);
                out_sm[tid] = o;
                if (cg == 0) outp[(row0 + tid) * 1024 + (t - 1)] = o;
            }
            float v0[16], v1[16];
            #pragma unroll
            for (int r = 0; r < 16; ++r) v0[r] = __ldcg(&g_hx[pr][row0 + r][tid]);
            #pragma unroll
            for (int r = 0; r < 16; ++r) v1[r] = __ldcg(&g_hx[pr][row0 + r][tid + 256]);
            #pragma unroll
            for (int r = 0; r < 16; ++r) {
                inpT[(9 + tid) * 18 + r]       = v0[r];
                inpT[(9 + tid + 256) * 18 + r] = v1[r];
            }
        }
        if (tid < 128) {
            int comp = tid & 7, r = tid >> 3;
            float xv = x[(row0 + r) * 8192 + t * 8 + comp];
            inpT[comp * 18 + r] = xv;
            if (comp == 0) x0s[r] = xv;
        }
        __syncthreads();
        // mass balance: s_t = s_{t-1} + x_t[0] - out_{t-1}
        if (tid < 16) {
            float s = s_sm[tid] + x0s[tid] - out_sm[tid];
            s_sm[tid] = s;
            inpT[8 * 18 + tid] = s;
            if (cg == 0) stop[(row0 + tid) * 1024 + t] = s;
        }
        __syncthreads();

        // ---- Phase C: mainloop. warp-private k range [warp*68, warp*68+68) ----
        unsigned long long acc[16];
        #pragma unroll
        for (int i = 0; i < 16; ++i) acc[i] = 0ull;
        {
            const float* Ip = inpT + warp * 68 * 18;
            const float* Wp = Wsm + warp * 68 * 64 + 2 * lane;
            #pragma unroll 4
            for (int kk = 0; kk < 68; ++kk) {
                unsigned long long ip[8];
                #pragma unroll
                for (int j = 0; j < 8; ++j)
                    ip[j] = *(const unsigned long long*)(Ip + kk * 18 + 2 * j);
                float2 wv = *(const float2*)(Wp + kk * 64);
                unsigned long long w00, w11;
                asm("mov.b64 %0, {%1, %1};" : "=l"(w00) : "f"(wv.x));
                asm("mov.b64 %0, {%1, %1};" : "=l"(w11) : "f"(wv.y));
                #pragma unroll
                for (int rp = 0; rp < 8; ++rp) {
                    asm("fma.rn.f32x2 %0, %1, %2, %0;" : "+l"(acc[2 * rp])     : "l"(ip[rp]), "l"(w00));
                    asm("fma.rn.f32x2 %0, %1, %2, %0;" : "+l"(acc[2 * rp + 1]) : "l"(ip[rp]), "l"(w11));
                }
            }
        }

        // ---- Phase D: reduce 8 k-partials, tanh, emit hx + readout partial ----
        #pragma unroll
        for (int rp = 0; rp < 8; ++rp) {
            float2 a0 = *(float2*)&acc[2 * rp];       // (.x=row 2rp, .y=row 2rp+1) col 2*lane
            float2 a1 = *(float2*)&acc[2 * rp + 1];   // col 2*lane+1
            *(float2*)&red[(warp * 16 + 2 * rp) * 68 + 2 * lane]     = make_float2(a0.x, a1.x);
            *(float2*)&red[(warp * 16 + 2 * rp + 1) * 68 + 2 * lane] = make_float2(a0.y, a1.y);
        }
        __syncthreads();
        {
            int r = tid >> 4, c4 = (tid & 15) * 4;
            float4 v = make_float4(0.f, 0.f, 0.f, 0.f);
            #pragma unroll
            for (int w = 0; w < 8; ++w) {
                float4 p = *(const float4*)&red[(w * 16 + r) * 68 + c4];
                v.x += p.x; v.y += p.y; v.z += p.z; v.w += p.w;
            }
            v.x = tanhf(v.x + b1s[c4 + 0]);
            v.y = tanhf(v.y + b1s[c4 + 1]);
            v.z = tanhf(v.z + b1s[c4 + 2]);
            v.w = tanhf(v.w + b1s[c4 + 3]);
            *(float4*)&g_hx[pw][row0 + r][cg * 64 + c4] = v;
            float p = v.x * w2s[c4] + v.y * w2s[c4 + 1] + v.z * w2s[c4 + 2] + v.w * w2s[c4 + 3];
            #pragma unroll
            for (int off = 8; off > 0; off >>= 1)
                p += __shfl_xor_sync(0xffffffffu, p, off);
            if ((tid & 15) == 0) g_part[pw][rg][cg][r] = p;
        }

        // ---- Phase E: cluster barrier (release on arrive / acquire on wait) ----
        asm volatile("barrier.cluster.arrive.aligned;" ::: "memory");
        asm volatile("barrier.cluster.wait.aligned;" ::: "memory");
    }

    // epilogue: final output value out_{L-1}
    if (cg == 0 && tid < 16) {
        float o = b2v;
        #pragma unroll
        for (int g = 0; g < 8; ++g) o += __ldcg(&g_part[1][rg][g][tid]);
        outp[(row0 + tid) * 1024 + 1023] = o;
    }
}

extern "C" void kernel_launch(void* const* d_in, const int* in_sizes, int n_in,
                              void* d_out, int out_size) {
    const float* x  = (const float*)d_in[0];
    const float* W1 = (const float*)d_in[1];
    const float* b1 = (const float*)d_in[2];
    const float* W2 = (const float*)d_in[3];
    const float* b2 = (const float*)d_in[4];
    float* out = (float*)d_out;

    cudaFuncSetAttribute(resRNN_kernel, cudaFuncAttributeMaxDynamicSharedMemorySize, SMEM_BYTES);

    dim3 grid(8, 16, 1);   // cluster_dims (8,1,1): one cluster per rowgroup
    dim3 block(TPB, 1, 1);
    resRNN_kernel<<<grid, block, SMEM_BYTES>>>(x, W1, b1, W2, b2, out);
}